// round 6
// baseline (speedup 1.0000x reference)
#include <cuda_runtime.h>
#include <cuda_bf16.h>
#include <cstdint>

// ---------------------------------------------------------------------------
// Embedding backward: dense_grad[idx[r], :] += grad[r, :] for idx[r] != 0.
//   grad:   [131072, 128] fp32 (identified by element count 131072*128)
//   idx:    [131072] int64 OR int32 (dtype auto-detected at runtime)
//   out:    [200000, 128] fp32, must be zeroed first (harness poisons 0xAA)
//
// Strategy:
//   1) cudaMemsetAsync zero of d_out (graph-capturable memset node).
//   2) 1-block dtype-detection kernel (int64 high words are all zero;
//      int32 data at odd word positions is ~never all zero).
//   3) scatter kernel: 1 warp per row, 1 float4 per lane, vectorized
//      red.global.add.v4.f32 (4x fewer L2 atomic ops than scalar atomicAdd).
// ---------------------------------------------------------------------------

__device__ int g_idx_is64;

__global__ void detect_idx_dtype_kernel(const unsigned int* __restrict__ w) {
    // Scan first 2048 index slots' high words (safe: int32 buffer is
    // 131072*4 bytes >= 16KB we touch).
    __shared__ int nonzero_high;
    if (threadIdx.x == 0) nonzero_high = 0;
    __syncthreads();
    for (int i = threadIdx.x; i < 2048; i += blockDim.x) {
        if (w[2 * i + 1] != 0u) nonzero_high = 1;  // benign race
    }
    __syncthreads();
    if (threadIdx.x == 0) g_idx_is64 = (nonzero_high == 0) ? 1 : 0;
}

__global__ void __launch_bounds__(256)
embedding_bwd_scatter_kernel(const float4* __restrict__ grad,
                             const void*   __restrict__ idx,
                             float*        __restrict__ out,
                             int nrows) {
    int t = blockIdx.x * blockDim.x + threadIdx.x;   // one float4 per thread
    int row = t >> 5;                                 // 32 lanes per row
    if (row >= nrows) return;

    long long index;
    if (g_idx_is64) {
        index = __ldg(reinterpret_cast<const long long*>(idx) + row);
    } else {
        index = (long long)__ldg(reinterpret_cast<const int*>(idx) + row);
    }
    if (index == 0) return;  // padding_idx contributes nothing

    float4 g = __ldg(grad + t);  // fully coalesced: t is contiguous

    float* dst = out + (long long)index * 128ll + (long long)(t & 31) * 4ll;
    // Vectorized reduction: 16B per L2 atomic op instead of 4B.
    asm volatile("red.global.add.v4.f32 [%0], {%1, %2, %3, %4};"
                 :: "l"(dst), "f"(g.x), "f"(g.y), "f"(g.z), "f"(g.w)
                 : "memory");
}

extern "C" void kernel_launch(void* const* d_in, const int* in_sizes, int n_in,
                              void* d_out, int out_size) {
    // Identify inputs by element count (robust to metadata ordering):
    //   grad_output: B*S*D elements (largest), indices: B*S, num_embeddings: 1.
    const float* grad = nullptr;
    const void*  idx  = nullptr;
    int nrows = 0;

    long long max_sz = -1;
    int grad_i = -1;
    for (int i = 0; i < n_in; i++) {
        if ((long long)in_sizes[i] > max_sz) { max_sz = in_sizes[i]; grad_i = i; }
    }
    grad = reinterpret_cast<const float*>(d_in[grad_i]);

    long long second = -1;
    int idx_i = -1;
    for (int i = 0; i < n_in; i++) {
        if (i == grad_i) continue;
        if ((long long)in_sizes[i] > second) { second = in_sizes[i]; idx_i = i; }
    }
    idx = d_in[idx_i];
    nrows = in_sizes[idx_i];

    // 1) Zero the dense gradient (output is poisoned with 0xAA).
    cudaMemsetAsync(d_out, 0, (size_t)out_size * sizeof(float), 0);

    // 2) Detect indices dtype (int64 vs int32).
    detect_idx_dtype_kernel<<<1, 256>>>(
        reinterpret_cast<const unsigned int*>(idx));

    // 3) Scatter-add.
    long long total_threads = (long long)nrows * 32ll;
    int block = 256;
    int gridd = (int)((total_threads + block - 1) / block);
    embedding_bwd_scatter_kernel<<<gridd, block>>>(
        reinterpret_cast<const float4*>(grad), idx,
        reinterpret_cast<float*>(d_out), nrows);
}